// round 11
// baseline (speedup 1.0000x reference)
#include <cuda_runtime.h>
#include <cuda_fp16.h>
#include <math.h>
#include <stdint.h>

#define N_NODES 10000
#define N_RELS  200
#define DIM     128
#define VIS_DIM 512
#define TXT_DIM 768
#define N_EDGES 320000
#define MAXDEG  128

// ---------------- scratch (static __device__, no allocs) ----------------
__device__ __half g_vf16[N_NODES * DIM];
__device__ __half g_tf16[N_NODES * DIM];

__device__ float  g_A[3][N_NODES * DIM];    // dst-side tables (fp32, read once per node)
__device__ __half g_Bh[3][N_NODES * DIM];   // src-side tables (fp16, gathered per edge)
__device__ __half g_Rh[3][N_RELS * DIM];    // relation tables (fp16, L1/L2 resident)
__device__ float4 g_asc4[N_NODES];          // packed w2.A per conv
__device__ float4 g_bsc4[N_NODES];          // packed w2.B per conv
__device__ float4 g_rsc4[N_RELS];           // packed w2.R per conv
__device__ int    g_counts[N_NODES];        // zero-initialized; aggregate resets after use
__device__ int2   g_bucket[N_NODES * MAXDEG];   // (src, edge_type)

__device__ __forceinline__ float lrelu(float x) { return x > 0.f ? x : 0.01f * x; }

// ---------------- bucket scatter: standalone, lightweight, full occupancy ----------------
__global__ void scatter_kernel(const int* __restrict__ src,
                               const int* __restrict__ dst,
                               const int* __restrict__ et) {
    int e0 = (blockIdx.x * blockDim.x + threadIdx.x) * 2;
    if (e0 >= N_EDGES) return;
    int2 d2 = *(const int2*)(dst + e0);
    int2 s2 = *(const int2*)(src + e0);
    int2 t2 = *(const int2*)(et + e0);
    int slot0 = atomicAdd(&g_counts[d2.x], 1);
    if (slot0 < MAXDEG) g_bucket[d2.x * MAXDEG + slot0] = make_int2(s2.x, t2.x);
    int slot1 = atomicAdd(&g_counts[d2.y], 1);
    if (slot1 < MAXDEG) g_bucket[d2.y * MAXDEG + slot1] = make_int2(s2.y, t2.y);
}

// ---------------- dtype-polymorphic 16-half loader (fp16 passthrough / fp32 convert) ----
__device__ __forceinline__ uint32_t pack2(float x, float y) {
    __half2 h = __floats2half2_rn(x, y);
    return *(uint32_t*)&h;
}
__device__ __forceinline__ void load16(const __half* p, uint4& a, uint4& b) {
    a = ((const uint4*)p)[0];
    b = ((const uint4*)p)[1];
}
__device__ __forceinline__ void load16(const float* p, uint4& a, uint4& b) {
    float4 f0 = ((const float4*)p)[0];
    float4 f1 = ((const float4*)p)[1];
    float4 f2 = ((const float4*)p)[2];
    float4 f3 = ((const float4*)p)[3];
    a.x = pack2(f0.x, f0.y); a.y = pack2(f0.z, f0.w);
    a.z = pack2(f1.x, f1.y); a.w = pack2(f1.z, f1.w);
    b.x = pack2(f2.x, f2.y); b.y = pack2(f2.z, f2.w);
    b.z = pack2(f3.x, f3.y); b.w = pack2(f3.z, f3.w);
}

// ---------------- tensor-core GEMM tile ----------------
#define MBK 32
#define XS  40    // padded smem row stride (halves)

__device__ __forceinline__ void ldm4(uint32_t& r0, uint32_t& r1, uint32_t& r2, uint32_t& r3,
                                     const __half* p) {
    uint32_t addr = (uint32_t)__cvta_generic_to_shared(p);
    asm volatile("ldmatrix.sync.aligned.m8n8.x4.shared.b16 {%0,%1,%2,%3}, [%4];"
                 : "=r"(r0), "=r"(r1), "=r"(r2), "=r"(r3) : "r"(addr));
}

__device__ __forceinline__ void mma16816(float* d, const uint32_t* a, uint32_t b0, uint32_t b1) {
    asm volatile("mma.sync.aligned.m16n8k16.row.col.f32.f16.f16.f32 "
                 "{%0,%1,%2,%3}, {%4,%5,%6,%7}, {%8,%9}, {%0,%1,%2,%3};"
                 : "+f"(d[0]), "+f"(d[1]), "+f"(d[2]), "+f"(d[3])
                 : "r"(a[0]), "r"(a[1]), "r"(a[2]), "r"(a[3]), "r"(b0), "r"(b1));
}

// C[row0:row0+128, 0:128] = X[M x K] @ W[128 x K]^T (+bias)
// outputs: optional fp32 Cf, optional fp16 Ch; optional rowdot sc[row*scstride] = w2 . row
template <class TX, class TW>
__device__ __forceinline__
void mma_tile(const TX* __restrict__ X, int M, int K, int ldx,
              const TW* __restrict__ W, int ldw,
              const float* __restrict__ bias,
              float* __restrict__ Cf, __half* __restrict__ Ch,
              const float* __restrict__ w2, float* __restrict__ sc, int scstride,
              int row0) {
    __shared__ __half sx[128 * XS];
    __shared__ __half sw[128 * XS];
    __shared__ float scbuf[128];

    int tid = threadIdx.x;
    int lane = tid & 31;
    int warp = tid >> 5;
    int wm = warp & 1;
    int wn = warp >> 1;

    int lrow = tid >> 1;
    int lcol = (tid & 1) * 16;

    float acc[4][4][4];
#pragma unroll
    for (int i = 0; i < 4; i++)
#pragma unroll
        for (int j = 0; j < 4; j++)
#pragma unroll
            for (int q = 0; q < 4; q++) acc[i][j][q] = 0.f;

    int rm = row0 + lrow; if (rm > M - 1) rm = M - 1;
    const TX* xp = X + (size_t)rm * ldx + lcol;
    const TW* wp = W + (size_t)lrow * ldw + lcol;

    uint4 px0, px1, pw0, pw1;
    load16(xp, px0, px1);
    load16(wp, pw0, pw1);

    int niter = K / MBK;
    for (int it = 0; it < niter; it++) {
        ((uint4*)(sx + lrow * XS + lcol))[0] = px0;
        ((uint4*)(sx + lrow * XS + lcol))[1] = px1;
        ((uint4*)(sw + lrow * XS + lcol))[0] = pw0;
        ((uint4*)(sw + lrow * XS + lcol))[1] = pw1;
        __syncthreads();

        if (it + 1 < niter) {
            int k0 = (it + 1) * MBK;
            load16(xp + k0, px0, px1);
            load16(wp + k0, pw0, pw1);
        }

#pragma unroll
        for (int ks = 0; ks < 2; ks++) {
            int k0 = ks * 16;
            uint32_t af[4][4];
#pragma unroll
            for (int mt = 0; mt < 4; mt++) {
                const __half* p = sx + (wm * 64 + mt * 16 + (lane & 15)) * XS
                                  + k0 + (lane >> 4) * 8;
                ldm4(af[mt][0], af[mt][1], af[mt][2], af[mt][3], p);
            }
            uint32_t bf[2][4];
#pragma unroll
            for (int bt = 0; bt < 2; bt++) {
                int nrow = wn * 32 + bt * 16 + (lane & 7) + ((lane >> 4) << 3);
                const __half* p = sw + nrow * XS + k0 + ((lane >> 3) & 1) * 8;
                ldm4(bf[bt][0], bf[bt][1], bf[bt][2], bf[bt][3], p);
            }
#pragma unroll
            for (int mt = 0; mt < 4; mt++)
#pragma unroll
                for (int nt = 0; nt < 4; nt++)
                    mma16816(acc[mt][nt], af[mt],
                             bf[nt >> 1][(nt & 1) * 2], bf[nt >> 1][(nt & 1) * 2 + 1]);
        }
        __syncthreads();
    }

    int gid = lane >> 2, tig = lane & 3;

    if (bias) {
#pragma unroll
        for (int nt = 0; nt < 4; nt++) {
            int col = wn * 32 + nt * 8 + tig * 2;
            float w0 = bias[col], w1 = bias[col + 1];
#pragma unroll
            for (int mt = 0; mt < 4; mt++) {
                acc[mt][nt][0] += w0; acc[mt][nt][1] += w1;
                acc[mt][nt][2] += w0; acc[mt][nt][3] += w1;
            }
        }
    }

    if (w2) {
        if (tid < 128) scbuf[tid] = 0.f;
        __syncthreads();
        float w2v[8];
#pragma unroll
        for (int nt = 0; nt < 4; nt++) {
            int col = wn * 32 + nt * 8 + tig * 2;
            w2v[2 * nt] = w2[col]; w2v[2 * nt + 1] = w2[col + 1];
        }
#pragma unroll
        for (int mt = 0; mt < 4; mt++) {
            float s1 = 0.f, s2 = 0.f;
#pragma unroll
            for (int nt = 0; nt < 4; nt++) {
                s1 += acc[mt][nt][0] * w2v[2 * nt] + acc[mt][nt][1] * w2v[2 * nt + 1];
                s2 += acc[mt][nt][2] * w2v[2 * nt] + acc[mt][nt][3] * w2v[2 * nt + 1];
            }
            s1 += __shfl_xor_sync(0xffffffffu, s1, 1);
            s1 += __shfl_xor_sync(0xffffffffu, s1, 2);
            s2 += __shfl_xor_sync(0xffffffffu, s2, 1);
            s2 += __shfl_xor_sync(0xffffffffu, s2, 2);
            if (tig == 0) {
                atomicAdd(&scbuf[wm * 64 + mt * 16 + gid], s1);
                atomicAdd(&scbuf[wm * 64 + mt * 16 + gid + 8], s2);
            }
        }
        __syncthreads();
        if (tid < 128 && row0 + tid < M) sc[(size_t)(row0 + tid) * scstride] = scbuf[tid];
    }

#pragma unroll
    for (int mt = 0; mt < 4; mt++) {
        int r1 = row0 + wm * 64 + mt * 16 + gid;
        int r2 = r1 + 8;
#pragma unroll
        for (int nt = 0; nt < 4; nt++) {
            int col = wn * 32 + nt * 8 + tig * 2;
            float c0 = acc[mt][nt][0], c1 = acc[mt][nt][1];
            float c2 = acc[mt][nt][2], c3 = acc[mt][nt][3];
            if (Cf) {
                if (r1 < M) *(float2*)(Cf + (size_t)r1 * DIM + col) = make_float2(c0, c1);
                if (r2 < M) *(float2*)(Cf + (size_t)r2 * DIM + col) = make_float2(c2, c3);
            }
            if (Ch) {
                if (r1 < M) *(__half2*)(Ch + (size_t)r1 * DIM + col) = __floats2half2_rn(c0, c1);
                if (r2 < M) *(__half2*)(Ch + (size_t)r2 * DIM + col) = __floats2half2_rn(c2, c3);
            }
        }
    }
}

#define GBN ((N_NODES + 127) / 128)

// ---- modality projections (fp32 inputs, fp16 out), convert fused into loads ----
__global__ __launch_bounds__(256, 2)
void proj_mma_kernel(const float* __restrict__ vis, const float* __restrict__ Wv,
                     const float* __restrict__ bv,
                     const float* __restrict__ txt, const float* __restrict__ Wt,
                     const float* __restrict__ bt) {
    int row0 = blockIdx.x * 128;
    if (blockIdx.z == 0)
        mma_tile<float, float>(vis, N_NODES, VIS_DIM, VIS_DIM, Wv, VIS_DIM, bv,
                               nullptr, g_vf16, nullptr, nullptr, 0, row0);
    else
        mma_tile<float, float>(txt, N_NODES, TXT_DIM, TXT_DIM, Wt, TXT_DIM, bt,
                               nullptr, g_tf16, nullptr, nullptr, 0, row0);
}

// ---- node tables (z=0..5) + relation tables (z=6) ----
__global__ __launch_bounds__(256, 2)
void node_rel_kernel(const float* __restrict__ s_emb, const float* __restrict__ rel_emb,
                     const float* __restrict__ W1s, const float* __restrict__ b1s,
                     const float* __restrict__ w2s,
                     const float* __restrict__ W1v, const float* __restrict__ b1v,
                     const float* __restrict__ w2v,
                     const float* __restrict__ W1t, const float* __restrict__ b1t,
                     const float* __restrict__ w2t) {
    int z = blockIdx.z;
    if (z < 6) {
        int c = z >> 1;          // conv
        int half = z & 1;        // 0=A(dst) 1=B(src)
        const float* W1 = (c == 0) ? W1s : (c == 1) ? W1v : W1t;
        const float* w2 = (c == 0) ? w2s : (c == 1) ? w2v : w2t;
        int row0 = blockIdx.x * 128;
        if (c == 0) {
            if (half == 0)
                mma_tile<float, float>(s_emb, N_NODES, DIM, DIM, W1, 384, nullptr,
                                       g_A[0], nullptr, w2, (float*)g_asc4 + 0, 4, row0);
            else
                mma_tile<float, float>(s_emb, N_NODES, DIM, DIM, W1 + 128, 384, nullptr,
                                       nullptr, g_Bh[0], w2, (float*)g_bsc4 + 0, 4, row0);
        } else {
            const __half* feat = (c == 1) ? g_vf16 : g_tf16;
            if (half == 0)
                mma_tile<__half, float>(feat, N_NODES, DIM, DIM, W1, 384, nullptr,
                                        g_A[c], nullptr, w2, (float*)g_asc4 + c, 4, row0);
            else
                mma_tile<__half, float>(feat, N_NODES, DIM, DIM, W1 + 128, 384, nullptr,
                                        nullptr, g_Bh[c], w2, (float*)g_bsc4 + c, 4, row0);
        }
    } else {
        if (blockIdx.x >= 6) return;
        int c = blockIdx.x >> 1;
        int row0 = (blockIdx.x & 1) * 128;
        const float* W1 = (c == 0) ? W1s : (c == 1) ? W1v : W1t;
        const float* b1 = (c == 0) ? b1s : (c == 1) ? b1v : b1t;
        const float* w2 = (c == 0) ? w2s : (c == 1) ? w2v : w2t;
        mma_tile<float, float>(rel_emb, N_RELS, DIM, DIM, W1 + 256, 384, b1,
                               nullptr, g_Rh[c], w2, (float*)g_rsc4 + c, 4, row0);
    }
}

// ---------------- fused aggregation: two-phase (edge-parallel logits, vector accumulate) ----
#define AGG_BLOCKS 1184    // 148 SMs x 8 resident blocks, grid-stride over nodes

__global__ __launch_bounds__(256)
void aggregate_kernel(const float* __restrict__ alpha_p,
                      const float* __restrict__ gamma_p,
                      float* __restrict__ out) {
    __shared__ float4 s_rsc[N_RELS];
    __shared__ float4 s_e[8][MAXDEG];      // per-warp edge weights (e0,e1,e2,-)
    for (int i = threadIdx.x; i < N_RELS; i += blockDim.x) s_rsc[i] = g_rsc4[i];
    __syncthreads();

    int wid = threadIdx.x >> 5;
    int lane = threadIdx.x & 31;
    int nwarps = gridDim.x * 8;
    float al = *alpha_p, ga = *gamma_p;
    float cs = 1.f - al - ga;

    const __half* B0 = g_Bh[0];
    const __half* B1 = g_Bh[1];
    const __half* B2 = g_Bh[2];
    const __half* R0 = g_Rh[0];
    const __half* R1 = g_Rh[1];
    const __half* R2 = g_Rh[2];
    int loff = lane * 4;

    for (int gw = blockIdx.x * 8 + wid; gw < N_NODES; gw += nwarps) {
        int cnt;
        if (lane == 0) {
            cnt = g_counts[gw];
            g_counts[gw] = 0;              // restore invariant for next replay
        }
        cnt = __shfl_sync(0xffffffffu, cnt, 0);
        if (cnt > MAXDEG) cnt = MAXDEG;
        const int2* bucket = g_bucket + (size_t)gw * MAXDEG;

        float4 av = g_asc4[gw];

        // ---- phase A: edge-parallel logit/exp, warp-reduced z ----
        float z0 = 0.f, z1 = 0.f, z2 = 0.f;
        for (int i = lane; i < cnt; i += 32) {
            int2 se = bucket[i];
            float4 bs = g_bsc4[se.x];
            float4 rs = s_rsc[se.y];
            float e0 = __expf(lrelu(av.x + bs.x + rs.x));
            float e1 = __expf(lrelu(av.y + bs.y + rs.y));
            float e2 = __expf(lrelu(av.z + bs.z + rs.z));
            s_e[wid][i] = make_float4(e0, e1, e2, 0.f);
            z0 += e0; z1 += e1; z2 += e2;
        }
#pragma unroll
        for (int o = 16; o > 0; o >>= 1) {
            z0 += __shfl_xor_sync(0xffffffffu, z0, o);
            z1 += __shfl_xor_sync(0xffffffffu, z1, o);
            z2 += __shfl_xor_sync(0xffffffffu, z2, o);
        }
        __syncwarp();

        // ---- phase B: vector accumulate with broadcast weights ----
        float4 acc0 = {0, 0, 0, 0}, acc1 = {0, 0, 0, 0}, acc2 = {0, 0, 0, 0};
        for (int i = 0; i < cnt; i++) {
            int2 se = bucket[i];             // L1-hot broadcast
            float4 ev = s_e[wid][i];         // smem broadcast
            int s = se.x, t = se.y;
            __half2 vb0a = *(const __half2*)(B0 + s * DIM + loff);
            __half2 vb0b = *(const __half2*)(B0 + s * DIM + loff + 2);
            __half2 vr0a = *(const __half2*)(R0 + t * DIM + loff);
            __half2 vr0b = *(const __half2*)(R0 + t * DIM + loff + 2);
            __half2 vb1a = *(const __half2*)(B1 + s * DIM + loff);
            __half2 vb1b = *(const __half2*)(B1 + s * DIM + loff + 2);
            __half2 vr1a = *(const __half2*)(R1 + t * DIM + loff);
            __half2 vr1b = *(const __half2*)(R1 + t * DIM + loff + 2);
            __half2 vb2a = *(const __half2*)(B2 + s * DIM + loff);
            __half2 vb2b = *(const __half2*)(B2 + s * DIM + loff + 2);
            __half2 vr2a = *(const __half2*)(R2 + t * DIM + loff);
            __half2 vr2b = *(const __half2*)(R2 + t * DIM + loff + 2);

            float2 t0a = __half22float2(__hadd2(vb0a, vr0a));
            float2 t0b = __half22float2(__hadd2(vb0b, vr0b));
            acc0.x += ev.x * t0a.x; acc0.y += ev.x * t0a.y;
            acc0.z += ev.x * t0b.x; acc0.w += ev.x * t0b.y;

            float2 t1a = __half22float2(__hadd2(vb1a, vr1a));
            float2 t1b = __half22float2(__hadd2(vb1b, vr1b));
            acc1.x += ev.y * t1a.x; acc1.y += ev.y * t1a.y;
            acc1.z += ev.y * t1b.x; acc1.w += ev.y * t1b.y;

            float2 t2a = __half22float2(__hadd2(vb2a, vr2a));
            float2 t2b = __half22float2(__hadd2(vb2b, vr2b));
            acc2.x += ev.z * t2a.x; acc2.y += ev.z * t2a.y;
            acc2.z += ev.z * t2b.x; acc2.w += ev.z * t2b.y;
        }

        float4 o = {0, 0, 0, 0};
        if (cnt > 0) {
            float4 A0 = ((const float4*)&g_A[0][gw * DIM])[lane];
            float4 A1 = ((const float4*)&g_A[1][gw * DIM])[lane];
            float4 A2 = ((const float4*)&g_A[2][gw * DIM])[lane];
            float iz0 = 1.f / z0, iz1 = 1.f / z1, iz2 = 1.f / z2;
            o.x = cs * lrelu(A0.x + acc0.x * iz0) + al * lrelu(A1.x + acc1.x * iz1) + ga * lrelu(A2.x + acc2.x * iz2);
            o.y = cs * lrelu(A0.y + acc0.y * iz0) + al * lrelu(A1.y + acc1.y * iz1) + ga * lrelu(A2.y + acc2.y * iz2);
            o.z = cs * lrelu(A0.z + acc0.z * iz0) + al * lrelu(A1.z + acc1.z * iz1) + ga * lrelu(A2.z + acc2.z * iz2);
            o.w = cs * lrelu(A0.w + acc0.w * iz0) + al * lrelu(A1.w + acc1.w * iz1) + ga * lrelu(A2.w + acc2.w * iz2);
        }
        ((float4*)(out + (size_t)gw * DIM))[lane] = o;
    }
}

// ---------------- host launcher ----------------
extern "C" void kernel_launch(void* const* d_in, const int* in_sizes, int n_in,
                              void* d_out, int out_size) {
    const int*   edge_index = (const int*)d_in[1];   // [2, E]
    const int*   edge_type  = (const int*)d_in[2];
    const float* visual     = (const float*)d_in[3];
    const float* textual    = (const float*)d_in[4];
    const float* s_emb      = (const float*)d_in[5];
    const float* rel_emb    = (const float*)d_in[6];
    const float* W1_s = (const float*)d_in[7];
    const float* b1_s = (const float*)d_in[8];
    const float* w2_s = (const float*)d_in[9];
    const float* W1_v = (const float*)d_in[10];
    const float* b1_v = (const float*)d_in[11];
    const float* w2_v = (const float*)d_in[12];
    const float* W1_t = (const float*)d_in[13];
    const float* b1_t = (const float*)d_in[14];
    const float* w2_t = (const float*)d_in[15];
    const float* Wv = (const float*)d_in[16];
    const float* bv = (const float*)d_in[17];
    const float* Wt = (const float*)d_in[18];
    const float* bt = (const float*)d_in[19];
    const float* alpha = (const float*)d_in[20];
    const float* gamma = (const float*)d_in[21];
    float* out = (float*)d_out;

    const int* src = edge_index;
    const int* dst = edge_index + N_EDGES;

    // launch 0: bucket scatter (lightweight, full occupancy)
    scatter_kernel<<<(N_EDGES / 2 + 255) / 256, 256>>>(src, dst, edge_type);

    // launch 1: modality projections (fp32 inputs converted in-register)
    proj_mma_kernel<<<dim3(GBN, 1, 2), 256>>>(visual, Wv, bv, textual, Wt, bt);

    // launch 2: node tables (z=0..5) + relation tables (z=6)
    node_rel_kernel<<<dim3(GBN, 1, 7), 256>>>(
        s_emb, rel_emb, W1_s, b1_s, w2_s, W1_v, b1_v, w2_v, W1_t, b1_t, w2_t);

    // launch 3: fused aggregation, grid-stride warps (also resets g_counts)
    aggregate_kernel<<<AGG_BLOCKS, 256>>>(alpha, gamma, out);
}

// round 12
// speedup vs baseline: 1.1228x; 1.1228x over previous
#include <cuda_runtime.h>
#include <cuda_fp16.h>
#include <math.h>
#include <stdint.h>

#define N_NODES 10000
#define N_RELS  200
#define DIM     128
#define VIS_DIM 512
#define TXT_DIM 768
#define N_EDGES 320000
#define MAXDEG  128

// ---------------- scratch (static __device__, no allocs) ----------------
__device__ __half g_vf16[N_NODES * DIM];
__device__ __half g_tf16[N_NODES * DIM];

__device__ float  g_A[3][N_NODES * DIM];    // dst-side tables (fp32, read once per node)
__device__ __half g_Bh[3][N_NODES * DIM];   // src-side tables (fp16, gathered per edge)
__device__ __half g_Rh[3][N_RELS * DIM];    // relation tables (fp16, L1/L2 resident)
__device__ float4 g_asc4[N_NODES];          // packed w2.A per conv
__device__ float4 g_bsc4[N_NODES];          // packed w2.B per conv
__device__ float4 g_rsc4[N_RELS];           // packed w2.R per conv
__device__ int    g_counts[N_NODES];        // zero-initialized; aggregate resets after use
__device__ int    g_bucket[N_NODES * MAXDEG];   // packed: src | (et << 16)

__device__ __forceinline__ float lrelu(float x) { return x > 0.f ? x : 0.01f * x; }

// ---------------- bucket scatter: standalone, lightweight, full occupancy ----------------
__global__ void scatter_kernel(const int* __restrict__ src,
                               const int* __restrict__ dst,
                               const int* __restrict__ et) {
    int e0 = (blockIdx.x * blockDim.x + threadIdx.x) * 2;
    if (e0 >= N_EDGES) return;
    int2 d2 = *(const int2*)(dst + e0);
    int2 s2 = *(const int2*)(src + e0);
    int2 t2 = *(const int2*)(et + e0);
    int slot0 = atomicAdd(&g_counts[d2.x], 1);
    if (slot0 < MAXDEG) g_bucket[d2.x * MAXDEG + slot0] = s2.x | (t2.x << 16);
    int slot1 = atomicAdd(&g_counts[d2.y], 1);
    if (slot1 < MAXDEG) g_bucket[d2.y * MAXDEG + slot1] = s2.y | (t2.y << 16);
}

// ---------------- dtype-polymorphic 16-half loader (fp16 passthrough / fp32 convert) ----
__device__ __forceinline__ uint32_t pack2(float x, float y) {
    __half2 h = __floats2half2_rn(x, y);
    return *(uint32_t*)&h;
}
__device__ __forceinline__ void load16(const __half* p, uint4& a, uint4& b) {
    a = ((const uint4*)p)[0];
    b = ((const uint4*)p)[1];
}
__device__ __forceinline__ void load16(const float* p, uint4& a, uint4& b) {
    float4 f0 = ((const float4*)p)[0];
    float4 f1 = ((const float4*)p)[1];
    float4 f2 = ((const float4*)p)[2];
    float4 f3 = ((const float4*)p)[3];
    a.x = pack2(f0.x, f0.y); a.y = pack2(f0.z, f0.w);
    a.z = pack2(f1.x, f1.y); a.w = pack2(f1.z, f1.w);
    b.x = pack2(f2.x, f2.y); b.y = pack2(f2.z, f2.w);
    b.z = pack2(f3.x, f3.y); b.w = pack2(f3.z, f3.w);
}

// ---------------- tensor-core GEMM tile ----------------
#define MBK 32
#define XS  40    // padded smem row stride (halves)

__device__ __forceinline__ void ldm4(uint32_t& r0, uint32_t& r1, uint32_t& r2, uint32_t& r3,
                                     const __half* p) {
    uint32_t addr = (uint32_t)__cvta_generic_to_shared(p);
    asm volatile("ldmatrix.sync.aligned.m8n8.x4.shared.b16 {%0,%1,%2,%3}, [%4];"
                 : "=r"(r0), "=r"(r1), "=r"(r2), "=r"(r3) : "r"(addr));
}

__device__ __forceinline__ void mma16816(float* d, const uint32_t* a, uint32_t b0, uint32_t b1) {
    asm volatile("mma.sync.aligned.m16n8k16.row.col.f32.f16.f16.f32 "
                 "{%0,%1,%2,%3}, {%4,%5,%6,%7}, {%8,%9}, {%0,%1,%2,%3};"
                 : "+f"(d[0]), "+f"(d[1]), "+f"(d[2]), "+f"(d[3])
                 : "r"(a[0]), "r"(a[1]), "r"(a[2]), "r"(a[3]), "r"(b0), "r"(b1));
}

// C[row0:row0+128, 0:128] = X[M x K] @ W[128 x K]^T (+bias)
// outputs: optional fp32 Cf, optional fp16 Ch; optional rowdot sc[row*scstride] = w2 . row
template <class TX, class TW>
__device__ __forceinline__
void mma_tile(const TX* __restrict__ X, int M, int K, int ldx,
              const TW* __restrict__ W, int ldw,
              const float* __restrict__ bias,
              float* __restrict__ Cf, __half* __restrict__ Ch,
              const float* __restrict__ w2, float* __restrict__ sc, int scstride,
              int row0) {
    __shared__ __half sx[128 * XS];
    __shared__ __half sw[128 * XS];
    __shared__ float scbuf[128];

    int tid = threadIdx.x;
    int lane = tid & 31;
    int warp = tid >> 5;
    int wm = warp & 1;
    int wn = warp >> 1;

    int lrow = tid >> 1;
    int lcol = (tid & 1) * 16;

    float acc[4][4][4];
#pragma unroll
    for (int i = 0; i < 4; i++)
#pragma unroll
        for (int j = 0; j < 4; j++)
#pragma unroll
            for (int q = 0; q < 4; q++) acc[i][j][q] = 0.f;

    int rm = row0 + lrow; if (rm > M - 1) rm = M - 1;
    const TX* xp = X + (size_t)rm * ldx + lcol;
    const TW* wp = W + (size_t)lrow * ldw + lcol;

    uint4 px0, px1, pw0, pw1;
    load16(xp, px0, px1);
    load16(wp, pw0, pw1);

    int niter = K / MBK;
    for (int it = 0; it < niter; it++) {
        ((uint4*)(sx + lrow * XS + lcol))[0] = px0;
        ((uint4*)(sx + lrow * XS + lcol))[1] = px1;
        ((uint4*)(sw + lrow * XS + lcol))[0] = pw0;
        ((uint4*)(sw + lrow * XS + lcol))[1] = pw1;
        __syncthreads();

        if (it + 1 < niter) {
            int k0 = (it + 1) * MBK;
            load16(xp + k0, px0, px1);
            load16(wp + k0, pw0, pw1);
        }

#pragma unroll
        for (int ks = 0; ks < 2; ks++) {
            int k0 = ks * 16;
            uint32_t af[4][4];
#pragma unroll
            for (int mt = 0; mt < 4; mt++) {
                const __half* p = sx + (wm * 64 + mt * 16 + (lane & 15)) * XS
                                  + k0 + (lane >> 4) * 8;
                ldm4(af[mt][0], af[mt][1], af[mt][2], af[mt][3], p);
            }
            uint32_t bf[2][4];
#pragma unroll
            for (int bt = 0; bt < 2; bt++) {
                int nrow = wn * 32 + bt * 16 + (lane & 7) + ((lane >> 4) << 3);
                const __half* p = sw + nrow * XS + k0 + ((lane >> 3) & 1) * 8;
                ldm4(bf[bt][0], bf[bt][1], bf[bt][2], bf[bt][3], p);
            }
#pragma unroll
            for (int mt = 0; mt < 4; mt++)
#pragma unroll
                for (int nt = 0; nt < 4; nt++)
                    mma16816(acc[mt][nt], af[mt],
                             bf[nt >> 1][(nt & 1) * 2], bf[nt >> 1][(nt & 1) * 2 + 1]);
        }
        __syncthreads();
    }

    int gid = lane >> 2, tig = lane & 3;

    if (bias) {
#pragma unroll
        for (int nt = 0; nt < 4; nt++) {
            int col = wn * 32 + nt * 8 + tig * 2;
            float w0 = bias[col], w1 = bias[col + 1];
#pragma unroll
            for (int mt = 0; mt < 4; mt++) {
                acc[mt][nt][0] += w0; acc[mt][nt][1] += w1;
                acc[mt][nt][2] += w0; acc[mt][nt][3] += w1;
            }
        }
    }

    if (w2) {
        if (tid < 128) scbuf[tid] = 0.f;
        __syncthreads();
        float w2v[8];
#pragma unroll
        for (int nt = 0; nt < 4; nt++) {
            int col = wn * 32 + nt * 8 + tig * 2;
            w2v[2 * nt] = w2[col]; w2v[2 * nt + 1] = w2[col + 1];
        }
#pragma unroll
        for (int mt = 0; mt < 4; mt++) {
            float s1 = 0.f, s2 = 0.f;
#pragma unroll
            for (int nt = 0; nt < 4; nt++) {
                s1 += acc[mt][nt][0] * w2v[2 * nt] + acc[mt][nt][1] * w2v[2 * nt + 1];
                s2 += acc[mt][nt][2] * w2v[2 * nt] + acc[mt][nt][3] * w2v[2 * nt + 1];
            }
            s1 += __shfl_xor_sync(0xffffffffu, s1, 1);
            s1 += __shfl_xor_sync(0xffffffffu, s1, 2);
            s2 += __shfl_xor_sync(0xffffffffu, s2, 1);
            s2 += __shfl_xor_sync(0xffffffffu, s2, 2);
            if (tig == 0) {
                atomicAdd(&scbuf[wm * 64 + mt * 16 + gid], s1);
                atomicAdd(&scbuf[wm * 64 + mt * 16 + gid + 8], s2);
            }
        }
        __syncthreads();
        if (tid < 128 && row0 + tid < M) sc[(size_t)(row0 + tid) * scstride] = scbuf[tid];
    }

#pragma unroll
    for (int mt = 0; mt < 4; mt++) {
        int r1 = row0 + wm * 64 + mt * 16 + gid;
        int r2 = r1 + 8;
#pragma unroll
        for (int nt = 0; nt < 4; nt++) {
            int col = wn * 32 + nt * 8 + tig * 2;
            float c0 = acc[mt][nt][0], c1 = acc[mt][nt][1];
            float c2 = acc[mt][nt][2], c3 = acc[mt][nt][3];
            if (Cf) {
                if (r1 < M) *(float2*)(Cf + (size_t)r1 * DIM + col) = make_float2(c0, c1);
                if (r2 < M) *(float2*)(Cf + (size_t)r2 * DIM + col) = make_float2(c2, c3);
            }
            if (Ch) {
                if (r1 < M) *(__half2*)(Ch + (size_t)r1 * DIM + col) = __floats2half2_rn(c0, c1);
                if (r2 < M) *(__half2*)(Ch + (size_t)r2 * DIM + col) = __floats2half2_rn(c2, c3);
            }
        }
    }
}

#define GBN ((N_NODES + 127) / 128)

// ---- modality projections (fp32 inputs, fp16 out), convert fused into loads ----
__global__ __launch_bounds__(256, 2)
void proj_mma_kernel(const float* __restrict__ vis, const float* __restrict__ Wv,
                     const float* __restrict__ bv,
                     const float* __restrict__ txt, const float* __restrict__ Wt,
                     const float* __restrict__ bt) {
    int row0 = blockIdx.x * 128;
    if (blockIdx.z == 0)
        mma_tile<float, float>(vis, N_NODES, VIS_DIM, VIS_DIM, Wv, VIS_DIM, bv,
                               nullptr, g_vf16, nullptr, nullptr, 0, row0);
    else
        mma_tile<float, float>(txt, N_NODES, TXT_DIM, TXT_DIM, Wt, TXT_DIM, bt,
                               nullptr, g_tf16, nullptr, nullptr, 0, row0);
}

// ---- node tables (z=0..5) + relation tables (z=6) ----
__global__ __launch_bounds__(256, 2)
void node_rel_kernel(const float* __restrict__ s_emb, const float* __restrict__ rel_emb,
                     const float* __restrict__ W1s, const float* __restrict__ b1s,
                     const float* __restrict__ w2s,
                     const float* __restrict__ W1v, const float* __restrict__ b1v,
                     const float* __restrict__ w2v,
                     const float* __restrict__ W1t, const float* __restrict__ b1t,
                     const float* __restrict__ w2t) {
    int z = blockIdx.z;
    if (z < 6) {
        int c = z >> 1;          // conv
        int half = z & 1;        // 0=A(dst) 1=B(src)
        const float* W1 = (c == 0) ? W1s : (c == 1) ? W1v : W1t;
        const float* w2 = (c == 0) ? w2s : (c == 1) ? w2v : w2t;
        int row0 = blockIdx.x * 128;
        if (c == 0) {
            if (half == 0)
                mma_tile<float, float>(s_emb, N_NODES, DIM, DIM, W1, 384, nullptr,
                                       g_A[0], nullptr, w2, (float*)g_asc4 + 0, 4, row0);
            else
                mma_tile<float, float>(s_emb, N_NODES, DIM, DIM, W1 + 128, 384, nullptr,
                                       nullptr, g_Bh[0], w2, (float*)g_bsc4 + 0, 4, row0);
        } else {
            const __half* feat = (c == 1) ? g_vf16 : g_tf16;
            if (half == 0)
                mma_tile<__half, float>(feat, N_NODES, DIM, DIM, W1, 384, nullptr,
                                        g_A[c], nullptr, w2, (float*)g_asc4 + c, 4, row0);
            else
                mma_tile<__half, float>(feat, N_NODES, DIM, DIM, W1 + 128, 384, nullptr,
                                        nullptr, g_Bh[c], w2, (float*)g_bsc4 + c, 4, row0);
        }
    } else {
        if (blockIdx.x >= 6) return;
        int c = blockIdx.x >> 1;
        int row0 = (blockIdx.x & 1) * 128;
        const float* W1 = (c == 0) ? W1s : (c == 1) ? W1v : W1t;
        const float* b1 = (c == 0) ? b1s : (c == 1) ? b1v : b1t;
        const float* w2 = (c == 0) ? w2s : (c == 1) ? w2v : w2t;
        mma_tile<float, float>(rel_emb, N_RELS, DIM, DIM, W1 + 256, 384, b1,
                               nullptr, g_Rh[c], w2, (float*)g_rsc4 + c, 4, row0);
    }
}

// ---------------- fused aggregation: half-warp edge-pairing, single pass ----------------
// Lanes 0-15 handle edge i, lanes 16-31 handle edge i+1. Each lane covers 8 halves
// (one uint4 per table). Scalar logit work replicated 16x (was 32x); gathers are 16B.
__device__ __forceinline__ void accum8(float* acc, float e, uint4 vb, uint4 vr) {
    __half2 h; float2 f;
    h = __hadd2(*(__half2*)&vb.x, *(__half2*)&vr.x); f = __half22float2(h);
    acc[0] += e * f.x; acc[1] += e * f.y;
    h = __hadd2(*(__half2*)&vb.y, *(__half2*)&vr.y); f = __half22float2(h);
    acc[2] += e * f.x; acc[3] += e * f.y;
    h = __hadd2(*(__half2*)&vb.z, *(__half2*)&vr.z); f = __half22float2(h);
    acc[4] += e * f.x; acc[5] += e * f.y;
    h = __hadd2(*(__half2*)&vb.w, *(__half2*)&vr.w); f = __half22float2(h);
    acc[6] += e * f.x; acc[7] += e * f.y;
}

__global__ __launch_bounds__(256)
void aggregate_kernel(const float* __restrict__ alpha_p,
                      const float* __restrict__ gamma_p,
                      float* __restrict__ out) {
    __shared__ float4 s_rsc[N_RELS];
    for (int i = threadIdx.x; i < N_RELS; i += blockDim.x) s_rsc[i] = g_rsc4[i];
    __syncthreads();

    int gw = (blockIdx.x * blockDim.x + threadIdx.x) >> 5;   // node id
    int lane = threadIdx.x & 31;
    if (gw >= N_NODES) return;

    int cnt = g_counts[gw];
    if (lane == 0) g_counts[gw] = 0;       // restore invariant for next replay
    if (cnt > MAXDEG) cnt = MAXDEG;
    const int* bucket = g_bucket + (size_t)gw * MAXDEG;

    float4 av = g_asc4[gw];

    int hw = lane >> 4;        // which edge of the pair
    int hl = lane & 15;        // position within half-warp
    int loff = hl * 8;         // 8 halves per lane

    const __half* B0 = g_Bh[0];
    const __half* B1 = g_Bh[1];
    const __half* B2 = g_Bh[2];
    const __half* R0 = g_Rh[0];
    const __half* R1 = g_Rh[1];
    const __half* R2 = g_Rh[2];

    float acc0[8] = {0, 0, 0, 0, 0, 0, 0, 0};
    float acc1[8] = {0, 0, 0, 0, 0, 0, 0, 0};
    float acc2[8] = {0, 0, 0, 0, 0, 0, 0, 0};
    float z0 = 0.f, z1 = 0.f, z2 = 0.f;

#pragma unroll 2
    for (int i = 0; i < cnt; i += 2) {
        int ei = i + hw;
        bool valid = (ei < cnt);
        int pk = bucket[valid ? ei : i];
        int s = pk & 0xFFFF;
        int t = pk >> 16;
        float vm = valid ? 1.f : 0.f;

        float4 bs = g_bsc4[s];
        float4 rs = s_rsc[t];
        float e0 = vm * __expf(lrelu(av.x + bs.x + rs.x));
        float e1 = vm * __expf(lrelu(av.y + bs.y + rs.y));
        float e2 = vm * __expf(lrelu(av.z + bs.z + rs.z));
        z0 += e0; z1 += e1; z2 += e2;

        uint4 vb0 = *(const uint4*)(B0 + s * DIM + loff);
        uint4 vr0 = *(const uint4*)(R0 + t * DIM + loff);
        uint4 vb1 = *(const uint4*)(B1 + s * DIM + loff);
        uint4 vr1 = *(const uint4*)(R1 + t * DIM + loff);
        uint4 vb2 = *(const uint4*)(B2 + s * DIM + loff);
        uint4 vr2 = *(const uint4*)(R2 + t * DIM + loff);

        accum8(acc0, e0, vb0, vr0);
        accum8(acc1, e1, vb1, vr1);
        accum8(acc2, e2, vb2, vr2);
    }

    // combine the two half-warps (each covered the same dims, different edges)
#pragma unroll
    for (int k = 0; k < 8; k++) {
        acc0[k] += __shfl_xor_sync(0xffffffffu, acc0[k], 16);
        acc1[k] += __shfl_xor_sync(0xffffffffu, acc1[k], 16);
        acc2[k] += __shfl_xor_sync(0xffffffffu, acc2[k], 16);
    }
    z0 += __shfl_xor_sync(0xffffffffu, z0, 16);
    z1 += __shfl_xor_sync(0xffffffffu, z1, 16);
    z2 += __shfl_xor_sync(0xffffffffu, z2, 16);

    float al = *alpha_p, ga = *gamma_p;
    float cs = 1.f - al - ga;
    int col = hl * 8 + hw * 4;           // this lane writes 4 dims
    int base = hw * 4;                   // which 4 of the lane's 8 accumulated dims
    float4 o = {0, 0, 0, 0};
    if (cnt > 0) {
        float4 A0 = *(const float4*)(&g_A[0][gw * DIM + col]);
        float4 A1 = *(const float4*)(&g_A[1][gw * DIM + col]);
        float4 A2 = *(const float4*)(&g_A[2][gw * DIM + col]);
        float iz0 = 1.f / z0, iz1 = 1.f / z1, iz2 = 1.f / z2;
        o.x = cs * lrelu(A0.x + acc0[base + 0] * iz0) + al * lrelu(A1.x + acc1[base + 0] * iz1) + ga * lrelu(A2.x + acc2[base + 0] * iz2);
        o.y = cs * lrelu(A0.y + acc0[base + 1] * iz0) + al * lrelu(A1.y + acc1[base + 1] * iz1) + ga * lrelu(A2.y + acc2[base + 1] * iz2);
        o.z = cs * lrelu(A0.z + acc0[base + 2] * iz0) + al * lrelu(A1.z + acc1[base + 2] * iz1) + ga * lrelu(A2.z + acc2[base + 2] * iz2);
        o.w = cs * lrelu(A0.w + acc0[base + 3] * iz0) + al * lrelu(A1.w + acc1[base + 3] * iz1) + ga * lrelu(A2.w + acc2[base + 3] * iz2);
    }
    *(float4*)(out + (size_t)gw * DIM + col) = o;
}

// ---------------- host launcher ----------------
extern "C" void kernel_launch(void* const* d_in, const int* in_sizes, int n_in,
                              void* d_out, int out_size) {
    const int*   edge_index = (const int*)d_in[1];   // [2, E]
    const int*   edge_type  = (const int*)d_in[2];
    const float* visual     = (const float*)d_in[3];
    const float* textual    = (const float*)d_in[4];
    const float* s_emb      = (const float*)d_in[5];
    const float* rel_emb    = (const float*)d_in[6];
    const float* W1_s = (const float*)d_in[7];
    const float* b1_s = (const float*)d_in[8];
    const float* w2_s = (const float*)d_in[9];
    const float* W1_v = (const float*)d_in[10];
    const float* b1_v = (const float*)d_in[11];
    const float* w2_v = (const float*)d_in[12];
    const float* W1_t = (const float*)d_in[13];
    const float* b1_t = (const float*)d_in[14];
    const float* w2_t = (const float*)d_in[15];
    const float* Wv = (const float*)d_in[16];
    const float* bv = (const float*)d_in[17];
    const float* Wt = (const float*)d_in[18];
    const float* bt = (const float*)d_in[19];
    const float* alpha = (const float*)d_in[20];
    const float* gamma = (const float*)d_in[21];
    float* out = (float*)d_out;

    const int* src = edge_index;
    const int* dst = edge_index + N_EDGES;

    // launch 0: bucket scatter (lightweight, full occupancy)
    scatter_kernel<<<(N_EDGES / 2 + 255) / 256, 256>>>(src, dst, edge_type);

    // launch 1: modality projections (fp32 inputs converted in-register)
    proj_mma_kernel<<<dim3(GBN, 1, 2), 256>>>(visual, Wv, bv, textual, Wt, bt);

    // launch 2: node tables (z=0..5) + relation tables (z=6)
    node_rel_kernel<<<dim3(GBN, 1, 7), 256>>>(
        s_emb, rel_emb, W1_s, b1_s, w2_s, W1_v, b1_v, w2_v, W1_t, b1_t, w2_t);

    // launch 3: fused aggregation, 1 warp per node, half-warp edge pairing
    aggregate_kernel<<<1250, 256>>>(alpha, gamma, out);
}